// round 2
// baseline (speedup 1.0000x reference)
#include <cuda_runtime.h>
#include <cuda_bf16.h>

#define N_NODES 50000
#define D 96
#define D4 (D / 4)          // 24 float4 per row
#define BM 64               // rows per MLP block

// Scratch: rst accumulator (init = feat, then scatter-added)
__device__ __align__(16) float g_rst[(size_t)N_NODES * D];

// ---------------------------------------------------------------------------
// Kernel 1: rst = feat  (vectorized copy)
// ---------------------------------------------------------------------------
__global__ void init_rst(const float4* __restrict__ feat, int n4) {
    int i = blockIdx.x * blockDim.x + threadIdx.x;
    if (i < n4) {
        reinterpret_cast<float4*>(g_rst)[i] = feat[i];
    }
}

// ---------------------------------------------------------------------------
// Kernel 2: rst[dst] += feat[src]  via vec4 L2 reductions.
// One thread per (edge, float4-chunk). Indices are INT32 (JAX downcasts
// int64 -> int32 without x64 mode).
// ---------------------------------------------------------------------------
__global__ void edge_scatter(const float* __restrict__ feat,
                             const int* __restrict__ src,
                             const int* __restrict__ dst,
                             int n_edges) {
    long long gid = (long long)blockIdx.x * blockDim.x + threadIdx.x;
    long long total = (long long)n_edges * D4;
    if (gid >= total) return;
    int e = (int)(gid / D4);
    int j = (int)(gid % D4);
    int s = src[e];
    int d = dst[e];
    float4 v = __ldg(reinterpret_cast<const float4*>(feat) + (size_t)s * D4 + j);
    float* p = g_rst + (size_t)d * D + j * 4;
    asm volatile("red.global.add.v4.f32 [%0], {%1, %2, %3, %4};"
                 :: "l"(p), "f"(v.x), "f"(v.y), "f"(v.z), "f"(v.w)
                 : "memory");
}

// ---------------------------------------------------------------------------
// Kernel 3: fused MLP  out = relu(rst @ W1 + b1) @ W2 + b2
// 256 threads, 64-row tile. W1, W2 (36 KB each) + X tile (padded) in dynamic
// smem. Each thread computes a 4x6 register tile. X tile is reused as the H
// tile between the two GEMM phases.
// ---------------------------------------------------------------------------
__global__ void __launch_bounds__(256, 2)
fused_mlp(const float* __restrict__ W1, const float* __restrict__ b1,
          const float* __restrict__ W2, const float* __restrict__ b2,
          float* __restrict__ Y, int nrows) {
    extern __shared__ float smem[];
    float* Ws1 = smem;                 // 96*96 = 9216 floats
    float* Ws2 = smem + 9216;          // 9216 floats
    float* Xs  = smem + 18432;         // BM * 97 = 6208 floats (padded rows)

    const int tid = threadIdx.x;       // 0..255
    const int tx  = tid & 15;          // col group: cols tx*6 .. tx*6+5
    const int ty  = tid >> 4;          // row group: rows ty*4 .. ty*4+3
    const int row0 = blockIdx.x * BM;

    // Stage W1, W2 (coalesced float4)
    {
        const float4* w1v = reinterpret_cast<const float4*>(W1);
        const float4* w2v = reinterpret_cast<const float4*>(W2);
        float4* s1v = reinterpret_cast<float4*>(Ws1);
        float4* s2v = reinterpret_cast<float4*>(Ws2);
        #pragma unroll
        for (int i = tid; i < 2304; i += 256) {   // 9216/4
            s1v[i] = w1v[i];
            s2v[i] = w2v[i];
        }
    }
    // Stage X tile (BM x 96 -> padded 97 per row)
    for (int i = tid; i < BM * D4; i += 256) {
        int r = i / D4, j = i % D4;
        int grow = row0 + r;
        float4 v = make_float4(0.f, 0.f, 0.f, 0.f);
        if (grow < nrows)
            v = __ldg(reinterpret_cast<const float4*>(g_rst) + (size_t)grow * D4 + j);
        float* p = Xs + r * 97 + j * 4;
        p[0] = v.x; p[1] = v.y; p[2] = v.z; p[3] = v.w;
    }
    __syncthreads();

    float acc[4][6];

    // ---- Phase 1: H = relu(X @ W1 + b1) ----
    #pragma unroll
    for (int i = 0; i < 4; i++)
        #pragma unroll
        for (int j = 0; j < 6; j++) acc[i][j] = 0.f;

    #pragma unroll 8
    for (int k = 0; k < D; k++) {
        float xr[4], wr[6];
        #pragma unroll
        for (int i = 0; i < 4; i++) xr[i] = Xs[(ty * 4 + i) * 97 + k];
        #pragma unroll
        for (int j = 0; j < 6; j++) wr[j] = Ws1[k * D + tx * 6 + j];
        #pragma unroll
        for (int i = 0; i < 4; i++)
            #pragma unroll
            for (int j = 0; j < 6; j++) acc[i][j] = fmaf(xr[i], wr[j], acc[i][j]);
    }

    float hreg[4][6];
    #pragma unroll
    for (int j = 0; j < 6; j++) {
        float bj = __ldg(b1 + tx * 6 + j);
        #pragma unroll
        for (int i = 0; i < 4; i++)
            hreg[i][j] = fmaxf(acc[i][j] + bj, 0.f);
    }

    __syncthreads();   // everyone done reading Xs
    #pragma unroll
    for (int i = 0; i < 4; i++)
        #pragma unroll
        for (int j = 0; j < 6; j++)
            Xs[(ty * 4 + i) * 97 + tx * 6 + j] = hreg[i][j];
    __syncthreads();

    // ---- Phase 2: Y = H @ W2 + b2 ----
    #pragma unroll
    for (int i = 0; i < 4; i++)
        #pragma unroll
        for (int j = 0; j < 6; j++) acc[i][j] = 0.f;

    #pragma unroll 8
    for (int k = 0; k < D; k++) {
        float xr[4], wr[6];
        #pragma unroll
        for (int i = 0; i < 4; i++) xr[i] = Xs[(ty * 4 + i) * 97 + k];
        #pragma unroll
        for (int j = 0; j < 6; j++) wr[j] = Ws2[k * D + tx * 6 + j];
        #pragma unroll
        for (int i = 0; i < 4; i++)
            #pragma unroll
            for (int j = 0; j < 6; j++) acc[i][j] = fmaf(xr[i], wr[j], acc[i][j]);
    }

    #pragma unroll
    for (int j = 0; j < 6; j++) {
        float bj = __ldg(b2 + tx * 6 + j);
        #pragma unroll
        for (int i = 0; i < 4; i++) {
            int grow = row0 + ty * 4 + i;
            if (grow < nrows)
                Y[(size_t)grow * D + tx * 6 + j] = acc[i][j] + bj;
        }
    }
}

// ---------------------------------------------------------------------------
// Launch
// ---------------------------------------------------------------------------
extern "C" void kernel_launch(void* const* d_in, const int* in_sizes, int n_in,
                              void* d_out, int out_size) {
    const float* feat = (const float*)d_in[0];
    const float* W1   = (const float*)d_in[1];
    const float* b1   = (const float*)d_in[2];
    const float* W2   = (const float*)d_in[3];
    const float* b2   = (const float*)d_in[4];
    const int* esrc   = (const int*)d_in[5];
    const int* edst   = (const int*)d_in[6];
    float* out = (float*)d_out;

    int n_edges = in_sizes[5];

    // 1) rst = feat
    int n4 = N_NODES * D / 4;  // 1,200,000
    init_rst<<<(n4 + 255) / 256, 256>>>((const float4*)feat, n4);

    // 2) rst[dst] += feat[src]
    long long work = (long long)n_edges * D4;
    int blocks = (int)((work + 255) / 256);
    edge_scatter<<<blocks, 256>>>(feat, esrc, edst, n_edges);

    // 3) fused MLP
    const int smem_bytes = (9216 + 9216 + BM * 97) * (int)sizeof(float); // 98560
    cudaFuncSetAttribute(fused_mlp, cudaFuncAttributeMaxDynamicSharedMemorySize,
                         smem_bytes);
    int mblocks = (N_NODES + BM - 1) / BM;  // 782
    fused_mlp<<<mblocks, 256, smem_bytes>>>(W1, b1, W2, b2, out, N_NODES);
}